// round 4
// baseline (speedup 1.0000x reference)
#include <cuda_runtime.h>
#include <cuda_bf16.h>
#include <math.h>

// Problem constants
#define TT 512
#define BB 128
#define DD 256
#define HH 512
#define G4 2048        // 4*H
#define MID 512
#define MAXROWS (TT*BB)   // 65536

// ---------------- scratch (device globals; allocation-free) ----------------
__device__ float g_xw[(size_t)MAXROWS * G4];     // 512 MB: x@W_ih^T + biases
__device__ float g_hs[(size_t)MAXROWS * HH];     // 128 MB: all hidden states
__device__ float g_hb[2][BB * HH];               // h double buffer
__device__ float g_c[BB * HH];                   // cell state (working copy)
__device__ int   g_offs[BB + 1];
__device__ int   g_rowb[MAXROWS];
__device__ int   g_rowt[MAXROWS];
__device__ float g_inp[(size_t)MAXROWS * (DD + HH)];  // packed MLP input [N,768]
__device__ float g_m1[(size_t)MAXROWS * MID];
__device__ float g_m2[(size_t)MAXROWS * MID];

// ---------------- small setup kernels ----------------
__global__ void scan_kernel(const int* __restrict__ len) {
    __shared__ int sl[BB];
    int tid = threadIdx.x;
    if (tid < BB) sl[tid] = len[tid];
    __syncthreads();
    if (tid == 0) {
        int s = 0;
        for (int b = 0; b < BB; b++) { g_offs[b] = s; s += sl[b]; }
        g_offs[BB] = s;
    }
}

__global__ void init_kernel(const float* __restrict__ h0, const float* __restrict__ c0) {
    int i = blockIdx.x * 256 + threadIdx.x;
    if (i < BB * HH) { g_hb[0][i] = h0[i]; g_c[i] = c0[i]; }
}

__global__ void rowmap_kernel(const int* __restrict__ len) {
    int b = blockIdx.x;
    int off = g_offs[b];
    int L = len[b];
    for (int i = threadIdx.x; i < L; i += blockDim.x) {
        g_rowb[off + i] = b;
        g_rowt[off + i] = i;
    }
}

// ---------------- generic SGEMM:  C[M,N] = act(A[M,K] @ W[N,K]^T + b1 + b2) --------
// Classic 128x128x8 tiling, 256 threads, 8x8 per-thread tile.
__global__ __launch_bounds__(256, 2) void sgemm_nt_bias(
    const float* __restrict__ A, const float* __restrict__ W,
    const float* __restrict__ bias1, const float* __restrict__ bias2,
    float* __restrict__ C, int M, int N, int K, int act)
{
    __shared__ float As[8][128];
    __shared__ float Ws[8][128];

    const int tid  = threadIdx.x;
    const int row0 = blockIdx.x * 128;
    const int col0 = blockIdx.y * 128;

    const int lr = tid >> 1;            // 0..127
    const int lc = (tid & 1) * 4;       // 0 or 4
    const int tx = tid & 15;
    const int ty = tid >> 4;

    float acc[8][8];
#pragma unroll
    for (int i = 0; i < 8; i++)
#pragma unroll
        for (int j = 0; j < 8; j++) acc[i][j] = 0.0f;

    const int  arow   = row0 + lr;
    const bool arow_ok = arow < M;
    const int  arow_c  = arow_ok ? arow : (M - 1);   // clamp: always a valid address
    const float* Ag = A + (size_t)arow_c * K + lc;
    const float* Wg = W + (size_t)(col0 + lr) * K + lc;

    for (int k0 = 0; k0 < K; k0 += 8) {
        float4 av = *(const float4*)(Ag + k0);
        if (!arow_ok) av = make_float4(0.f, 0.f, 0.f, 0.f);
        float4 wv = *(const float4*)(Wg + k0);
        As[lc + 0][lr] = av.x; As[lc + 1][lr] = av.y;
        As[lc + 2][lr] = av.z; As[lc + 3][lr] = av.w;
        Ws[lc + 0][lr] = wv.x; Ws[lc + 1][lr] = wv.y;
        Ws[lc + 2][lr] = wv.z; Ws[lc + 3][lr] = wv.w;
        __syncthreads();
#pragma unroll
        for (int kk = 0; kk < 8; kk++) {
            float a[8], b[8];
            *(float4*)(a)     = *(const float4*)&As[kk][ty * 8];
            *(float4*)(a + 4) = *(const float4*)&As[kk][ty * 8 + 4];
            *(float4*)(b)     = *(const float4*)&Ws[kk][tx * 8];
            *(float4*)(b + 4) = *(const float4*)&Ws[kk][tx * 8 + 4];
#pragma unroll
            for (int i = 0; i < 8; i++)
#pragma unroll
                for (int j = 0; j < 8; j++) acc[i][j] += a[i] * b[j];
        }
        __syncthreads();
    }

    float bsum[8];
#pragma unroll
    for (int j = 0; j < 8; j++) {
        int c = col0 + tx * 8 + j;
        bsum[j] = bias1[c] + (bias2 ? bias2[c] : 0.0f);
    }
#pragma unroll
    for (int i = 0; i < 8; i++) {
        int r = row0 + ty * 8 + i;
        if (r < M) {
            float outv[8];
#pragma unroll
            for (int j = 0; j < 8; j++) {
                float v = acc[i][j] + bsum[j];
                if (act == 1) v = fmaxf(v, 0.0f);
                outv[j] = v;
            }
            *(float4*)(&C[(size_t)r * N + col0 + tx * 8])     = *(float4*)(outv);
            *(float4*)(&C[(size_t)r * N + col0 + tx * 8 + 4]) = *(float4*)(outv + 4);
        }
    }
}

// ---------------- LSTM step kernel (fused gates + pointwise) ----------------
// Grid: 128 CTAs, each owns 4 hidden units (all 4 gates) x all 128 batch rows.
// Block: 128 threads; thread (tx=tid&3, ty=tid>>2) computes rows ty*4..+3
// for unit u0+tx, gates i/f/g/o.  W_hh slice cached in SMEM for whole K.
__global__ __launch_bounds__(128) void lstm_step_kernel(int t, const float* __restrict__ W_hh)
{
    __shared__ float sW[512 * 16];   // [k][q] q = tx*4 + gate  (32 KB)
    __shared__ float sH[16 * 132];   // [kk][row] padded        (8.25 KB)

    const int tid = threadIdx.x;
    const int u0  = blockIdx.x * 4;
    const int tx  = tid & 3;
    const int ty  = tid >> 2;        // 0..31

    const float* hprev = g_hb[t & 1];
    float*       hnext = g_hb[(t + 1) & 1];

    // Load W_hh rows for this CTA's 16 gate-columns into SMEM, k-major.
    {
        int q  = tid & 15;           // q = du*4 + g
        int g  = q & 3;
        int du = q >> 2;
        int kb = (tid >> 4) * 64;    // 8 groups of 64 k
        const float* wrow = W_hh + (size_t)(g * HH + u0 + du) * HH + kb;
#pragma unroll
        for (int i = 0; i < 16; i++) {
            float4 w4 = *(const float4*)(wrow + i * 4);
            int k = kb + i * 4;
            sW[(k + 0) * 16 + q] = w4.x;
            sW[(k + 1) * 16 + q] = w4.y;
            sW[(k + 2) * 16 + q] = w4.z;
            sW[(k + 3) * 16 + q] = w4.w;
        }
    }

    // acc[r][g]: init from precomputed xw (x@W_ih^T + b_ih + b_hh)
    float acc[4][4];
    const float* xwrow = g_xw + (size_t)t * BB * G4;
#pragma unroll
    for (int r = 0; r < 4; r++) {
        int row = ty * 4 + r;
#pragma unroll
        for (int g = 0; g < 4; g++)
            acc[r][g] = xwrow[(size_t)row * G4 + g * HH + u0 + tx];
    }
    __syncthreads();   // sW ready

    for (int k0 = 0; k0 < HH; k0 += 16) {
        // stage h chunk [128 rows x 16 k] -> sH[kk][row]
        {
            int kc    = (tid & 3) * 4;
            int rbase = tid >> 2;
#pragma unroll
            for (int i = 0; i < 4; i++) {
                int row = rbase + i * 32;
                float4 h4 = *(const float4*)(hprev + (size_t)row * HH + k0 + kc);
                sH[(kc + 0) * 132 + row] = h4.x;
                sH[(kc + 1) * 132 + row] = h4.y;
                sH[(kc + 2) * 132 + row] = h4.z;
                sH[(kc + 3) * 132 + row] = h4.w;
            }
        }
        __syncthreads();
#pragma unroll
        for (int kk = 0; kk < 16; kk++) {
            float4 hv = *(const float4*)&sH[kk * 132 + ty * 4];
            float4 wv = *(const float4*)&sW[(k0 + kk) * 16 + tx * 4];
            acc[0][0] += hv.x * wv.x; acc[0][1] += hv.x * wv.y;
            acc[0][2] += hv.x * wv.z; acc[0][3] += hv.x * wv.w;
            acc[1][0] += hv.y * wv.x; acc[1][1] += hv.y * wv.y;
            acc[1][2] += hv.y * wv.z; acc[1][3] += hv.y * wv.w;
            acc[2][0] += hv.z * wv.x; acc[2][1] += hv.z * wv.y;
            acc[2][2] += hv.z * wv.z; acc[2][3] += hv.z * wv.w;
            acc[3][0] += hv.w * wv.x; acc[3][1] += hv.w * wv.y;
            acc[3][2] += hv.w * wv.z; acc[3][3] += hv.w * wv.w;
        }
        __syncthreads();
    }

    // pointwise: c' = sig(f)*c + sig(i)*tanh(g);  h = sig(o)*tanh(c')
    const int u = u0 + tx;
#pragma unroll
    for (int r = 0; r < 4; r++) {
        int row = ty * 4 + r;
        float gi = acc[r][0], gf = acc[r][1], gg = acc[r][2], go = acc[r][3];
        float si = 1.0f / (1.0f + __expf(-gi));
        float sf = 1.0f / (1.0f + __expf(-gf));
        float so = 1.0f / (1.0f + __expf(-go));
        float tg = tanhf(gg);
        float c  = sf * g_c[(size_t)row * HH + u] + si * tg;
        g_c[(size_t)row * HH + u] = c;
        float h = so * tanhf(c);
        hnext[(size_t)row * HH + u] = h;
        g_hs[((size_t)t * BB + row) * HH + u] = h;
    }
}

// ---------------- ragged pack: inp[r] = concat(state[t,b,:], hs[t,b,:]) ----------
__global__ void pack_kernel(const float* __restrict__ state, int N)
{
    int idx = blockIdx.x * 256 + threadIdx.x;      // float4 index
    if (idx >= N * 192) return;                    // 192 = (256+512)/4
    int r = idx / 192;
    int c = idx % 192;
    int b = g_rowb[r];
    int t = g_rowt[r];
    float4 v;
    if (c < 64) v = *(const float4*)(state + ((size_t)(t * BB + b)) * DD + c * 4);
    else        v = *(const float4*)(g_hs + ((size_t)(t * BB + b)) * HH + (c - 64) * 4);
    *(float4*)(g_inp + (size_t)r * (DD + HH) + c * 4) = v;
}

// ---------------- thin output heads (3-wide actor / 1-wide critic) ----------------
__global__ void head_kernel(const float* __restrict__ X, const float* __restrict__ Wh,
                            const float* __restrict__ bh, float* __restrict__ out,
                            int N, int nout, int do_tanh)
{
    __shared__ float sw[3 * 512];
    int tid = threadIdx.x;
    for (int i = tid; i < nout * 512; i += 256) sw[i] = Wh[i];
    __syncthreads();
    int warp = tid >> 5, lane = tid & 31;
    int r = blockIdx.x * 8 + warp;
    if (r >= N) return;
    const float* x = X + (size_t)r * 512;
    float s0 = 0.f, s1 = 0.f, s2 = 0.f;
    for (int k = lane; k < 512; k += 32) {
        float v = x[k];
        s0 += v * sw[k];
        if (nout > 1) { s1 += v * sw[512 + k]; s2 += v * sw[1024 + k]; }
    }
#pragma unroll
    for (int o = 16; o; o >>= 1) {
        s0 += __shfl_xor_sync(0xffffffffu, s0, o);
        s1 += __shfl_xor_sync(0xffffffffu, s1, o);
        s2 += __shfl_xor_sync(0xffffffffu, s2, o);
    }
    if (lane == 0) {
        float v0 = s0 + bh[0]; if (do_tanh) v0 = tanhf(v0);
        out[(size_t)r * nout + 0] = v0;
        if (nout > 1) {
            float v1 = s1 + bh[1]; if (do_tanh) v1 = tanhf(v1);
            float v2 = s2 + bh[2]; if (do_tanh) v2 = tanhf(v2);
            out[(size_t)r * nout + 1] = v1;
            out[(size_t)r * nout + 2] = v2;
        }
    }
}

// ---------------- launch ----------------
extern "C" void kernel_launch(void* const* d_in, const int* in_sizes, int n_in,
                              void* d_out, int out_size)
{
    const float* state = (const float*)d_in[0];
    const float* h0    = (const float*)d_in[1];
    const float* c0    = (const float*)d_in[2];
    const int*   lens  = (const int*)  d_in[3];
    const float* W_ih  = (const float*)d_in[4];
    const float* W_hh  = (const float*)d_in[5];
    const float* b_ih  = (const float*)d_in[6];
    const float* b_hh  = (const float*)d_in[7];
    const float* aw0 = (const float*)d_in[8];  const float* ab0 = (const float*)d_in[9];
    const float* aw1 = (const float*)d_in[10]; const float* ab1 = (const float*)d_in[11];
    const float* aw2 = (const float*)d_in[12]; const float* ab2 = (const float*)d_in[13];
    const float* cw0 = (const float*)d_in[14]; const float* cb0 = (const float*)d_in[15];
    const float* cw1 = (const float*)d_in[16]; const float* cb1 = (const float*)d_in[17];
    const float* cw2 = (const float*)d_in[18]; const float* cb2 = (const float*)d_in[19];
    float* out = (float*)d_out;

    const int N = out_size / 4;   // actor 3N + critic N

    float *p_xw, *p_inp, *p_m1, *p_m2;
    cudaGetSymbolAddress((void**)&p_xw,  g_xw);
    cudaGetSymbolAddress((void**)&p_inp, g_inp);
    cudaGetSymbolAddress((void**)&p_m1,  g_m1);
    cudaGetSymbolAddress((void**)&p_m2,  g_m2);

    scan_kernel<<<1, 128>>>(lens);
    init_kernel<<<(BB * HH + 255) / 256, 256>>>(h0, c0);
    rowmap_kernel<<<BB, 128>>>(lens);

    // xw = state @ W_ih^T + b_ih + b_hh   for all T*B rows
    sgemm_nt_bias<<<dim3(MAXROWS / 128, G4 / 128), 256>>>(
        state, W_ih, b_ih, b_hh, p_xw, MAXROWS, G4, DD, 0);

    for (int t = 0; t < TT; t++)
        lstm_step_kernel<<<BB, 128>>>(t, W_hh);

    pack_kernel<<<(N * 192 + 255) / 256, 256>>>(state, N);

    dim3 gmlp((N + 127) / 128, MID / 128);
    // actor
    sgemm_nt_bias<<<gmlp, 256>>>(p_inp, aw0, ab0, nullptr, p_m1, N, MID, DD + HH, 1);
    sgemm_nt_bias<<<gmlp, 256>>>(p_m1,  aw1, ab1, nullptr, p_m2, N, MID, MID, 1);
    head_kernel<<<(N + 7) / 8, 256>>>(p_m2, aw2, ab2, out, N, 3, 1);
    // critic
    sgemm_nt_bias<<<gmlp, 256>>>(p_inp, cw0, cb0, nullptr, p_m1, N, MID, DD + HH, 1);
    sgemm_nt_bias<<<gmlp, 256>>>(p_m1,  cw1, cb1, nullptr, p_m2, N, MID, MID, 1);
    head_kernel<<<(N + 7) / 8, 256>>>(p_m2, cw2, cb2, out + (size_t)3 * N, N, 1, 0);
}